// round 2
// baseline (speedup 1.0000x reference)
#include <cuda_runtime.h>

#define Bn 4
#define Tn 2048
#define Cn 1024
#define Hn 16
#define Dn 64

// Scratch in [B, H, T, D] layout
__device__ float g_Q[Bn * Hn * Tn * Dn];
__device__ float g_K[Bn * Hn * Tn * Dn];
__device__ float g_V[Bn * Hn * Tn * Dn];
__device__ float g_A[Bn * Hn * Tn * Dn];

// ---------------------------------------------------------------------------
// QKV projection: Y = X @ W, written to [B,H,T,D]
// Tile 64x64, BK=16, 256 threads, 4x4 per thread.
// ---------------------------------------------------------------------------
__global__ __launch_bounds__(256) void qkv_gemm_kernel(
    const float* __restrict__ X,
    const float* __restrict__ Wq,
    const float* __restrict__ Wk,
    const float* __restrict__ Wv)
{
    __shared__ float As[16][68];  // [kk][m]
    __shared__ float Bs[16][68];  // [kk][n]

    const int z = blockIdx.z;
    const float* __restrict__ W = (z == 0) ? Wq : (z == 1) ? Wk : Wv;
    float* __restrict__ Y = (z == 0) ? g_Q : (z == 1) ? g_K : g_V;

    const int tid = threadIdx.x;
    const int tx = tid & 15, ty = tid >> 4;
    const int m0 = blockIdx.y << 6, n0 = blockIdx.x << 6;

    const int arow = tid >> 2, akq = (tid & 3) << 2;
    const int brow = tid >> 4, bcq = (tid & 15) << 2;

    float acc[4][4] = {};

    for (int k0 = 0; k0 < Cn; k0 += 16) {
        float4 a = *(const float4*)&X[(m0 + arow) * Cn + k0 + akq];
        As[akq + 0][arow] = a.x;
        As[akq + 1][arow] = a.y;
        As[akq + 2][arow] = a.z;
        As[akq + 3][arow] = a.w;
        float4 bv = *(const float4*)&W[(k0 + brow) * Cn + n0 + bcq];
        *(float4*)&Bs[brow][bcq] = bv;
        __syncthreads();
#pragma unroll
        for (int kk = 0; kk < 16; kk++) {
            float4 av = *(const float4*)&As[kk][ty << 2];
            float4 bb = *(const float4*)&Bs[kk][tx << 2];
            float ar[4] = {av.x, av.y, av.z, av.w};
            float br[4] = {bb.x, bb.y, bb.z, bb.w};
#pragma unroll
            for (int i = 0; i < 4; i++)
#pragma unroll
                for (int j = 0; j < 4; j++)
                    acc[i][j] += ar[i] * br[j];
        }
        __syncthreads();
    }

    // write to [B, H, T, D]; n0 is a multiple of 64 so one head per block
    const int h = n0 >> 6;
    const int d = tx << 2;
#pragma unroll
    for (int i = 0; i < 4; i++) {
        int m = m0 + (ty << 2) + i;
        int b = m >> 11, t = m & (Tn - 1);
        float4 o = {acc[i][0], acc[i][1], acc[i][2], acc[i][3]};
        *(float4*)&Y[((b * Hn + h) * Tn + t) * Dn + d] = o;
    }
}

// ---------------------------------------------------------------------------
// Flash attention: one block = 64 queries of one (b, h); causal.
// ---------------------------------------------------------------------------
#define SM_QT 0
#define SM_KT (64 * 68)
#define SM_VS (2 * 64 * 68)
#define SM_SS (3 * 64 * 68)
#define SM_M (3 * 64 * 68 + 64 * 65)
#define SM_L (SM_M + 64)
#define SM_C (SM_L + 64)
#define SMEM_FLOATS (SM_C + 64)
#define SMEM_BYTES (SMEM_FLOATS * 4)

__global__ __launch_bounds__(256) void flash_attn_kernel()
{
    extern __shared__ float sm[];
    float* Qt = sm + SM_QT;   // [d][row], pitch 68
    float* Kt = sm + SM_KT;   // [d][key], pitch 68
    float* Vs = sm + SM_VS;   // [key][d], pitch 68
    float* Ss = sm + SM_SS;   // [row][key], pitch 65
    float* mrow = sm + SM_M;
    float* lrow = sm + SM_L;
    float* crow = sm + SM_C;

    const int qb = blockIdx.x;             // 0..31
    const int h = blockIdx.y, b = blockIdx.z;
    const int tid = threadIdx.x;
    const int tx = tid & 15, ty = tid >> 4;
    const int q0 = qb << 6;

    const float* __restrict__ Qg = g_Q + (b * Hn + h) * Tn * Dn;
    const float* __restrict__ Kg = g_K + (b * Hn + h) * Tn * Dn;
    const float* __restrict__ Vg = g_V + (b * Hn + h) * Tn * Dn;

    const int lrow_idx = tid >> 2;             // 0..63 (row of tile)
    const int ldq = (tid & 3) << 2;            // 0,4,8,12

    // load Q tile transposed: 64 rows x 64 cols needs 4 float4 per thread
#pragma unroll
    for (int it = 0; it < 4; it++) {
        int c = ldq + (it << 4);               // 0..60
        float4 q = *(const float4*)&Qg[(q0 + lrow_idx) * Dn + c];
        Qt[(c + 0) * 68 + lrow_idx] = q.x;
        Qt[(c + 1) * 68 + lrow_idx] = q.y;
        Qt[(c + 2) * 68 + lrow_idx] = q.z;
        Qt[(c + 3) * 68 + lrow_idx] = q.w;
    }
    if (tid < 64) {
        mrow[tid] = -1e30f;
        lrow[tid] = 0.0f;
    }

    float o[4][4] = {};
    __syncthreads();

    for (int kb = 0; kb <= qb; kb++) {
        const int k0 = kb << 6;
        // load K (transposed) and V (direct): 4 float4 per thread each
#pragma unroll
        for (int it = 0; it < 4; it++) {
            int c = ldq + (it << 4);
            float4 kv = *(const float4*)&Kg[(k0 + lrow_idx) * Dn + c];
            Kt[(c + 0) * 68 + lrow_idx] = kv.x;
            Kt[(c + 1) * 68 + lrow_idx] = kv.y;
            Kt[(c + 2) * 68 + lrow_idx] = kv.z;
            Kt[(c + 3) * 68 + lrow_idx] = kv.w;
            float4 vv = *(const float4*)&Vg[(k0 + lrow_idx) * Dn + c];
            *(float4*)&Vs[lrow_idx * 68 + c] = vv;
        }
        __syncthreads();

        // S = Q @ K^T
        float s[4][4] = {};
#pragma unroll 16
        for (int d = 0; d < 64; d++) {
            float4 av = *(const float4*)&Qt[d * 68 + (ty << 2)];
            float4 bb = *(const float4*)&Kt[d * 68 + (tx << 2)];
            float ar[4] = {av.x, av.y, av.z, av.w};
            float br[4] = {bb.x, bb.y, bb.z, bb.w};
#pragma unroll
            for (int i = 0; i < 4; i++)
#pragma unroll
                for (int j = 0; j < 4; j++)
                    s[i][j] += ar[i] * br[j];
        }
        const bool diag = (kb == qb);
#pragma unroll
        for (int i = 0; i < 4; i++) {
            int qr = (ty << 2) + i;
#pragma unroll
            for (int j = 0; j < 4; j++) {
                int kc = (tx << 2) + j;
                float v = s[i][j] * 0.125f;  // 1/sqrt(64)
                if (diag && kc > qr) v = -1e30f;
                Ss[qr * 65 + kc] = v;
            }
        }
        __syncthreads();

        // online softmax: 4 threads per row
        {
            const int r = tid >> 2, g = tid & 3;
            const int cbase = g << 4;
            float mold = mrow[r];
            float mt = -1e30f;
#pragma unroll
            for (int c = 0; c < 16; c++)
                mt = fmaxf(mt, Ss[r * 65 + cbase + c]);
            mt = fmaxf(mt, __shfl_xor_sync(0xffffffffu, mt, 1));
            mt = fmaxf(mt, __shfl_xor_sync(0xffffffffu, mt, 2));
            float mnew = fmaxf(mold, mt);
            float psum = 0.0f;
#pragma unroll
            for (int c = 0; c < 16; c++) {
                float p = __expf(Ss[r * 65 + cbase + c] - mnew);
                Ss[r * 65 + cbase + c] = p;
                psum += p;
            }
            psum += __shfl_xor_sync(0xffffffffu, psum, 1);
            psum += __shfl_xor_sync(0xffffffffu, psum, 2);
            if (g == 0) {
                float cf = __expf(mold - mnew);
                lrow[r] = lrow[r] * cf + psum;
                mrow[r] = mnew;
                crow[r] = cf;
            }
        }
        __syncthreads();

        // rescale O, then O += P @ V
#pragma unroll
        for (int i = 0; i < 4; i++) {
            float cf = crow[(ty << 2) + i];
#pragma unroll
            for (int j = 0; j < 4; j++)
                o[i][j] *= cf;
        }
#pragma unroll 16
        for (int k = 0; k < 64; k++) {
            float ar[4];
#pragma unroll
            for (int i = 0; i < 4; i++)
                ar[i] = Ss[((ty << 2) + i) * 65 + k];
            float4 bb = *(const float4*)&Vs[k * 68 + (tx << 2)];
            float br[4] = {bb.x, bb.y, bb.z, bb.w};
#pragma unroll
            for (int i = 0; i < 4; i++)
#pragma unroll
                for (int j = 0; j < 4; j++)
                    o[i][j] += ar[i] * br[j];
        }
        __syncthreads();  // protect Kt/Vs/Ss for next iteration
    }

    // normalize and write to g_A [B,H,T,D]
    float* __restrict__ Ag = g_A + (b * Hn + h) * Tn * Dn;
#pragma unroll
    for (int i = 0; i < 4; i++) {
        int qr = (ty << 2) + i;
        float inv = 1.0f / lrow[qr];
        float4 ov = {o[i][0] * inv, o[i][1] * inv, o[i][2] * inv, o[i][3] * inv};
        *(float4*)&Ag[(q0 + qr) * Dn + (tx << 2)] = ov;
    }
}

// ---------------------------------------------------------------------------
// Output projection: out = A2 @ Wo + bo, A2[m][c] gathered from [B,H,T,D]
// ---------------------------------------------------------------------------
__global__ __launch_bounds__(256) void oproj_kernel(
    const float* __restrict__ Wo,
    const float* __restrict__ bo,
    float* __restrict__ out)
{
    __shared__ float As[16][68];
    __shared__ float Bs[16][68];

    const int tid = threadIdx.x;
    const int tx = tid & 15, ty = tid >> 4;
    const int m0 = blockIdx.y << 6, n0 = blockIdx.x << 6;

    const int arow = tid >> 2, akq = (tid & 3) << 2;
    const int brow = tid >> 4, bcq = (tid & 15) << 2;

    const int am = m0 + arow;
    const int ab = am >> 11, at = am & (Tn - 1);

    float acc[4][4] = {};

    for (int k0 = 0; k0 < Cn; k0 += 16) {
        int k = k0 + akq;
        int h = k >> 6, d = k & 63;
        float4 a = *(const float4*)&g_A[((ab * Hn + h) * Tn + at) * Dn + d];
        As[akq + 0][arow] = a.x;
        As[akq + 1][arow] = a.y;
        As[akq + 2][arow] = a.z;
        As[akq + 3][arow] = a.w;
        float4 bv = *(const float4*)&Wo[(k0 + brow) * Cn + n0 + bcq];
        *(float4*)&Bs[brow][bcq] = bv;
        __syncthreads();
#pragma unroll
        for (int kk = 0; kk < 16; kk++) {
            float4 av = *(const float4*)&As[kk][ty << 2];
            float4 bb = *(const float4*)&Bs[kk][tx << 2];
            float ar[4] = {av.x, av.y, av.z, av.w};
            float br[4] = {bb.x, bb.y, bb.z, bb.w};
#pragma unroll
            for (int i = 0; i < 4; i++)
#pragma unroll
                for (int j = 0; j < 4; j++)
                    acc[i][j] += ar[i] * br[j];
        }
        __syncthreads();
    }

    float4 bias = *(const float4*)&bo[n0 + (tx << 2)];
#pragma unroll
    for (int i = 0; i < 4; i++) {
        int m = m0 + (ty << 2) + i;
        float4 ov = {acc[i][0] + bias.x, acc[i][1] + bias.y,
                     acc[i][2] + bias.z, acc[i][3] + bias.w};
        *(float4*)&out[m * Cn + n0 + (tx << 2)] = ov;
    }
}

// ---------------------------------------------------------------------------
extern "C" void kernel_launch(void* const* d_in, const int* in_sizes, int n_in,
                              void* d_out, int out_size)
{
    const float* x  = (const float*)d_in[0];
    const float* Wq = (const float*)d_in[1];
    const float* Wk = (const float*)d_in[2];
    const float* Wv = (const float*)d_in[3];
    const float* Wo = (const float*)d_in[4];
    const float* bo = (const float*)d_in[5];
    float* out = (float*)d_out;

    cudaFuncSetAttribute(flash_attn_kernel,
                         cudaFuncAttributeMaxDynamicSharedMemorySize, SMEM_BYTES);

    dim3 gq(Cn / 64, (Bn * Tn) / 64, 3);
    qkv_gemm_kernel<<<gq, 256>>>(x, Wq, Wk, Wv);

    dim3 ga(Tn / 64, Hn, Bn);
    flash_attn_kernel<<<ga, 256, SMEM_BYTES>>>();

    dim3 go(Cn / 64, (Bn * Tn) / 64);
    oproj_kernel<<<go, 256>>>(Wo, bo, out);
}

// round 3
// speedup vs baseline: 3.0264x; 3.0264x over previous
#include <cuda_runtime.h>

#define Bn 4
#define Tn 2048
#define Cn 1024
#define Hn 16
#define Dn 64

// Scratch in [B, H, T, D] layout (fp32)
__device__ float g_Q[Bn * Hn * Tn * Dn];
__device__ float g_K[Bn * Hn * Tn * Dn];
__device__ float g_V[Bn * Hn * Tn * Dn];
__device__ float g_A[Bn * Hn * Tn * Dn];

__device__ __forceinline__ unsigned f2tf(float f) {
    unsigned u;
    asm("cvt.rna.tf32.f32 %0, %1;" : "=r"(u) : "f"(f));
    return u;
}

__device__ __forceinline__ void mma_tf32(float* c, const unsigned* a, const unsigned* b) {
    asm volatile(
        "mma.sync.aligned.m16n8k8.row.col.f32.tf32.tf32.f32 "
        "{%0,%1,%2,%3}, {%4,%5,%6,%7}, {%8,%9}, {%0,%1,%2,%3};\n"
        : "+f"(c[0]), "+f"(c[1]), "+f"(c[2]), "+f"(c[3])
        : "r"(a[0]), "r"(a[1]), "r"(a[2]), "r"(a[3]), "r"(b[0]), "r"(b[1]));
}

// ---------------------------------------------------------------------------
// QKV projection: Y = X @ W -> [B,H,T,D].  Block 128x128, BK=16, 8 warps.
// Warp tile 64x32 (4 m16-tiles x 4 n8-tiles).
// ---------------------------------------------------------------------------
__global__ __launch_bounds__(256) void qkv_mma_kernel(
    const float* __restrict__ X,
    const float* __restrict__ Wq,
    const float* __restrict__ Wk,
    const float* __restrict__ Wv)
{
    __shared__ unsigned As[128][20];   // [m][k], tf32 bits, pitch 20
    __shared__ unsigned Bs[16][136];   // [k][n], tf32 bits, pitch 136

    const int z = blockIdx.z;
    const float* __restrict__ W = (z == 0) ? Wq : (z == 1) ? Wk : Wv;
    float* __restrict__ Y = (z == 0) ? g_Q : (z == 1) ? g_K : g_V;

    const int tid = threadIdx.x;
    const int lane = tid & 31, wid = tid >> 5;
    const int g = lane >> 2, t = lane & 3;
    const int warpm = wid >> 2, warpn = wid & 3;
    const int m0 = blockIdx.y << 7, n0 = blockIdx.x << 7;

    const int rowA = tid >> 2, kq = tid & 3;    // A: 2 float4 (rows rowA, rowA+64)
    const int krow = tid >> 5, nq = tid & 31;   // B: 2 float4 (k-rows krow, krow+8)

    float4 ra0 = *(const float4*)&X[(size_t)(m0 + rowA) * Cn + kq * 4];
    float4 ra1 = *(const float4*)&X[(size_t)(m0 + rowA + 64) * Cn + kq * 4];
    float4 rb0 = *(const float4*)&W[(size_t)krow * Cn + n0 + nq * 4];
    float4 rb1 = *(const float4*)&W[(size_t)(krow + 8) * Cn + n0 + nq * 4];

    float c[4][4][4] = {};

    for (int k0 = 0; k0 < Cn; k0 += 16) {
        uint4 u;
        u.x = f2tf(ra0.x); u.y = f2tf(ra0.y); u.z = f2tf(ra0.z); u.w = f2tf(ra0.w);
        *(uint4*)&As[rowA][kq * 4] = u;
        u.x = f2tf(ra1.x); u.y = f2tf(ra1.y); u.z = f2tf(ra1.z); u.w = f2tf(ra1.w);
        *(uint4*)&As[rowA + 64][kq * 4] = u;
        u.x = f2tf(rb0.x); u.y = f2tf(rb0.y); u.z = f2tf(rb0.z); u.w = f2tf(rb0.w);
        *(uint4*)&Bs[krow][nq * 4] = u;
        u.x = f2tf(rb1.x); u.y = f2tf(rb1.y); u.z = f2tf(rb1.z); u.w = f2tf(rb1.w);
        *(uint4*)&Bs[krow + 8][nq * 4] = u;
        __syncthreads();

        if (k0 + 16 < Cn) {
            ra0 = *(const float4*)&X[(size_t)(m0 + rowA) * Cn + k0 + 16 + kq * 4];
            ra1 = *(const float4*)&X[(size_t)(m0 + rowA + 64) * Cn + k0 + 16 + kq * 4];
            rb0 = *(const float4*)&W[(size_t)(k0 + 16 + krow) * Cn + n0 + nq * 4];
            rb1 = *(const float4*)&W[(size_t)(k0 + 24 + krow) * Cn + n0 + nq * 4];
        }

#pragma unroll
        for (int ks = 0; ks < 2; ks++) {
            const int kk = ks * 8;
            unsigned a[4][4], b[4][2];
#pragma unroll
            for (int mi = 0; mi < 4; mi++) {
                const int mr = warpm * 64 + mi * 16;
                a[mi][0] = As[mr + g][kk + t];
                a[mi][1] = As[mr + g + 8][kk + t];
                a[mi][2] = As[mr + g][kk + t + 4];
                a[mi][3] = As[mr + g + 8][kk + t + 4];
            }
#pragma unroll
            for (int nj = 0; nj < 4; nj++) {
                const int nc = warpn * 32 + nj * 8;
                b[nj][0] = Bs[kk + t][nc + g];
                b[nj][1] = Bs[kk + t + 4][nc + g];
            }
#pragma unroll
            for (int mi = 0; mi < 4; mi++)
#pragma unroll
                for (int nj = 0; nj < 4; nj++)
                    mma_tf32(c[mi][nj], a[mi], b[nj]);
        }
        __syncthreads();
    }

    // write [B,H,T,D]
#pragma unroll
    for (int mi = 0; mi < 4; mi++) {
#pragma unroll
        for (int r = 0; r < 2; r++) {
            const int row = m0 + warpm * 64 + mi * 16 + g + 8 * r;
            const int b_ = row >> 11, t_ = row & (Tn - 1);
#pragma unroll
            for (int nj = 0; nj < 4; nj++) {
                const int n = n0 + warpn * 32 + nj * 8 + 2 * t;
                const int h = n >> 6, d = n & 63;
                float2 v = {c[mi][nj][2 * r], c[mi][nj][2 * r + 1]};
                *(float2*)&Y[(size_t)((b_ * Hn + h) * Tn + t_) * Dn + d] = v;
            }
        }
    }
}

// ---------------------------------------------------------------------------
// Flash attention with tf32 mma: Br=Bc=64, 4 warps, Q in registers.
// ---------------------------------------------------------------------------
#define AP 72
#define FLASH_SMEM_BYTES (3 * 64 * AP * 4)

__global__ __launch_bounds__(128) void flash_mma_kernel()
{
    extern __shared__ unsigned smf[];
    unsigned* Ks = smf;                 // [key][d] pitch AP (also Q staging)
    unsigned* Vs = smf + 64 * AP;       // [key][d] pitch AP
    unsigned* Ps = smf + 2 * 64 * AP;   // [q][key] pitch AP

    const int qb = blockIdx.x;
    const int h = blockIdx.y, b = blockIdx.z;
    const int tid = threadIdx.x;
    const int lane = tid & 31, wid = tid >> 5;
    const int g = lane >> 2, t = lane & 3;
    const int q0 = qb << 6;

    const size_t base = (size_t)((b * Hn + h) * Tn) * Dn;
    const float* __restrict__ Qg = g_Q + base;
    const float* __restrict__ Kg = g_K + base;
    const float* __restrict__ Vg = g_V + base;

    const int lrow = tid >> 4;          // 0..7 step over 64 rows (8 iters)
    const int lc = (tid & 15) * 4;      // float4 col

    // stage Q into Ks, then lift to A-fragments in registers
#pragma unroll
    for (int i = 0; i < 8; i++) {
        const int row = lrow + i * 8;
        float4 v = *(const float4*)&Qg[(size_t)(q0 + row) * Dn + lc];
        uint4 u = {f2tf(v.x), f2tf(v.y), f2tf(v.z), f2tf(v.w)};
        *(uint4*)&Ks[row * AP + lc] = u;
    }
    __syncthreads();

    unsigned qa[8][4];
    const int qrow = wid * 16 + g;
#pragma unroll
    for (int ks = 0; ks < 8; ks++) {
        qa[ks][0] = Ks[qrow * AP + ks * 8 + t];
        qa[ks][1] = Ks[(qrow + 8) * AP + ks * 8 + t];
        qa[ks][2] = Ks[qrow * AP + ks * 8 + t + 4];
        qa[ks][3] = Ks[(qrow + 8) * AP + ks * 8 + t + 4];
    }
    __syncthreads();

    float o[8][4] = {};
    float m0v = -1e30f, m1v = -1e30f, l0 = 0.0f, l1 = 0.0f;

    for (int kb = 0; kb <= qb; kb++) {
        const int k0 = kb << 6;
        // load K and V tiles (tf32)
#pragma unroll
        for (int i = 0; i < 8; i++) {
            const int row = lrow + i * 8;
            float4 kv = *(const float4*)&Kg[(size_t)(k0 + row) * Dn + lc];
            uint4 uk = {f2tf(kv.x), f2tf(kv.y), f2tf(kv.z), f2tf(kv.w)};
            *(uint4*)&Ks[row * AP + lc] = uk;
            float4 vv = *(const float4*)&Vg[(size_t)(k0 + row) * Dn + lc];
            uint4 uv = {f2tf(vv.x), f2tf(vv.y), f2tf(vv.z), f2tf(vv.w)};
            *(uint4*)&Vs[row * AP + lc] = uv;
        }
        __syncthreads();

        // S = Q @ K^T  (B-frag: b0 = K[nj*8+g][ks*8+t])
        float s[8][4] = {};
#pragma unroll
        for (int ks = 0; ks < 8; ks++) {
#pragma unroll
            for (int nj = 0; nj < 8; nj++) {
                unsigned bb[2];
                bb[0] = Ks[(nj * 8 + g) * AP + ks * 8 + t];
                bb[1] = Ks[(nj * 8 + g) * AP + ks * 8 + t + 4];
                mma_tf32(s[nj], qa[ks], bb);
            }
        }

        // softmax (registers + quad shuffles); rows qrow, qrow+8
        const bool diag = (kb == qb);
        float mt0 = -1e30f, mt1 = -1e30f;
#pragma unroll
        for (int nj = 0; nj < 8; nj++) {
#pragma unroll
            for (int e = 0; e < 4; e++) s[nj][e] *= 0.125f;
            if (diag) {
                const int col0 = nj * 8 + 2 * t, col1 = col0 + 1;
                if (col0 > qrow) s[nj][0] = -1e30f;
                if (col1 > qrow) s[nj][1] = -1e30f;
                if (col0 > qrow + 8) s[nj][2] = -1e30f;
                if (col1 > qrow + 8) s[nj][3] = -1e30f;
            }
            mt0 = fmaxf(mt0, fmaxf(s[nj][0], s[nj][1]));
            mt1 = fmaxf(mt1, fmaxf(s[nj][2], s[nj][3]));
        }
        mt0 = fmaxf(mt0, __shfl_xor_sync(0xffffffffu, mt0, 1));
        mt0 = fmaxf(mt0, __shfl_xor_sync(0xffffffffu, mt0, 2));
        mt1 = fmaxf(mt1, __shfl_xor_sync(0xffffffffu, mt1, 1));
        mt1 = fmaxf(mt1, __shfl_xor_sync(0xffffffffu, mt1, 2));

        const float mn0 = fmaxf(m0v, mt0);
        const float mn1 = fmaxf(m1v, mt1);
        float sum0 = 0.0f, sum1 = 0.0f;
#pragma unroll
        for (int nj = 0; nj < 8; nj++) {
            float p0 = __expf(s[nj][0] - mn0);
            float p1 = __expf(s[nj][1] - mn0);
            float p2 = __expf(s[nj][2] - mn1);
            float p3 = __expf(s[nj][3] - mn1);
            sum0 += p0 + p1;
            sum1 += p2 + p3;
            uint2 w0 = {f2tf(p0), f2tf(p1)};
            *(uint2*)&Ps[qrow * AP + nj * 8 + 2 * t] = w0;
            uint2 w1 = {f2tf(p2), f2tf(p3)};
            *(uint2*)&Ps[(qrow + 8) * AP + nj * 8 + 2 * t] = w1;
        }
        sum0 += __shfl_xor_sync(0xffffffffu, sum0, 1);
        sum0 += __shfl_xor_sync(0xffffffffu, sum0, 2);
        sum1 += __shfl_xor_sync(0xffffffffu, sum1, 1);
        sum1 += __shfl_xor_sync(0xffffffffu, sum1, 2);

        const float cf0 = __expf(m0v - mn0);
        const float cf1 = __expf(m1v - mn1);
        l0 = l0 * cf0 + sum0;
        l1 = l1 * cf1 + sum1;
        m0v = mn0;
        m1v = mn1;
#pragma unroll
        for (int nj = 0; nj < 8; nj++) {
            o[nj][0] *= cf0; o[nj][1] *= cf0;
            o[nj][2] *= cf1; o[nj][3] *= cf1;
        }
        __syncwarp();

        // O += P @ V  (A-frag from Ps, B-frag: b0 = V[ks*8+t][nj*8+g])
#pragma unroll
        for (int ks = 0; ks < 8; ks++) {
            unsigned pa[4];
            pa[0] = Ps[qrow * AP + ks * 8 + t];
            pa[1] = Ps[(qrow + 8) * AP + ks * 8 + t];
            pa[2] = Ps[qrow * AP + ks * 8 + t + 4];
            pa[3] = Ps[(qrow + 8) * AP + ks * 8 + t + 4];
#pragma unroll
            for (int nj = 0; nj < 8; nj++) {
                unsigned bb[2];
                bb[0] = Vs[(ks * 8 + t) * AP + nj * 8 + g];
                bb[1] = Vs[(ks * 8 + t + 4) * AP + nj * 8 + g];
                mma_tf32(o[nj], pa, bb);
            }
        }
        __syncthreads();
    }

    // normalize + write g_A
    float* __restrict__ Ag = g_A + base;
    const float inv0 = 1.0f / l0, inv1 = 1.0f / l1;
#pragma unroll
    for (int nj = 0; nj < 8; nj++) {
        const int d = nj * 8 + 2 * t;
        float2 v0 = {o[nj][0] * inv0, o[nj][1] * inv0};
        *(float2*)&Ag[(size_t)(q0 + qrow) * Dn + d] = v0;
        float2 v1 = {o[nj][2] * inv1, o[nj][3] * inv1};
        *(float2*)&Ag[(size_t)(q0 + qrow + 8) * Dn + d] = v1;
    }
}

// ---------------------------------------------------------------------------
// Output projection: out = A @ Wo + bo (A gathered from [B,H,T,D])
// ---------------------------------------------------------------------------
__global__ __launch_bounds__(256) void oproj_mma_kernel(
    const float* __restrict__ Wo,
    const float* __restrict__ bo,
    float* __restrict__ out)
{
    __shared__ unsigned As[128][20];
    __shared__ unsigned Bs[16][136];

    const int tid = threadIdx.x;
    const int lane = tid & 31, wid = tid >> 5;
    const int g = lane >> 2, t = lane & 3;
    const int warpm = wid >> 2, warpn = wid & 3;
    const int m0 = blockIdx.y << 7, n0 = blockIdx.x << 7;

    const int rowA = tid >> 2, kq = tid & 3;
    const int krow = tid >> 5, nq = tid & 31;

    const int mA0 = m0 + rowA, mA1 = m0 + rowA + 64;
    const int ab0 = mA0 >> 11, at0 = mA0 & (Tn - 1);
    const int ab1 = mA1 >> 11, at1 = mA1 & (Tn - 1);

    auto loadA = [&](int bb, int tt, int k) {
        const int hh = k >> 6, dd = k & 63;
        return *(const float4*)&g_A[(size_t)((bb * Hn + hh) * Tn + tt) * Dn + dd];
    };

    float4 ra0 = loadA(ab0, at0, kq * 4);
    float4 ra1 = loadA(ab1, at1, kq * 4);
    float4 rb0 = *(const float4*)&Wo[(size_t)krow * Cn + n0 + nq * 4];
    float4 rb1 = *(const float4*)&Wo[(size_t)(krow + 8) * Cn + n0 + nq * 4];

    float c[4][4][4] = {};

    for (int k0 = 0; k0 < Cn; k0 += 16) {
        uint4 u;
        u.x = f2tf(ra0.x); u.y = f2tf(ra0.y); u.z = f2tf(ra0.z); u.w = f2tf(ra0.w);
        *(uint4*)&As[rowA][kq * 4] = u;
        u.x = f2tf(ra1.x); u.y = f2tf(ra1.y); u.z = f2tf(ra1.z); u.w = f2tf(ra1.w);
        *(uint4*)&As[rowA + 64][kq * 4] = u;
        u.x = f2tf(rb0.x); u.y = f2tf(rb0.y); u.z = f2tf(rb0.z); u.w = f2tf(rb0.w);
        *(uint4*)&Bs[krow][nq * 4] = u;
        u.x = f2tf(rb1.x); u.y = f2tf(rb1.y); u.z = f2tf(rb1.z); u.w = f2tf(rb1.w);
        *(uint4*)&Bs[krow + 8][nq * 4] = u;
        __syncthreads();

        if (k0 + 16 < Cn) {
            ra0 = loadA(ab0, at0, k0 + 16 + kq * 4);
            ra1 = loadA(ab1, at1, k0 + 16 + kq * 4);
            rb0 = *(const float4*)&Wo[(size_t)(k0 + 16 + krow) * Cn + n0 + nq * 4];
            rb1 = *(const float4*)&Wo[(size_t)(k0 + 24 + krow) * Cn + n0 + nq * 4];
        }

#pragma unroll
        for (int ks = 0; ks < 2; ks++) {
            const int kk = ks * 8;
            unsigned a[4][4], b[4][2];
#pragma unroll
            for (int mi = 0; mi < 4; mi++) {
                const int mr = warpm * 64 + mi * 16;
                a[mi][0] = As[mr + g][kk + t];
                a[mi][1] = As[mr + g + 8][kk + t];
                a[mi][2] = As[mr + g][kk + t + 4];
                a[mi][3] = As[mr + g + 8][kk + t + 4];
            }
#pragma unroll
            for (int nj = 0; nj < 4; nj++) {
                const int nc = warpn * 32 + nj * 8;
                b[nj][0] = Bs[kk + t][nc + g];
                b[nj][1] = Bs[kk + t + 4][nc + g];
            }
#pragma unroll
            for (int mi = 0; mi < 4; mi++)
#pragma unroll
                for (int nj = 0; nj < 4; nj++)
                    mma_tf32(c[mi][nj], a[mi], b[nj]);
        }
        __syncthreads();
    }

#pragma unroll
    for (int mi = 0; mi < 4; mi++) {
#pragma unroll
        for (int r = 0; r < 2; r++) {
            const int row = m0 + warpm * 64 + mi * 16 + g + 8 * r;
#pragma unroll
            for (int nj = 0; nj < 4; nj++) {
                const int n = n0 + warpn * 32 + nj * 8 + 2 * t;
                float2 bias = *(const float2*)&bo[n];
                float2 v = {c[mi][nj][2 * r] + bias.x, c[mi][nj][2 * r + 1] + bias.y};
                *(float2*)&out[(size_t)row * Cn + n] = v;
            }
        }
    }
}

// ---------------------------------------------------------------------------
extern "C" void kernel_launch(void* const* d_in, const int* in_sizes, int n_in,
                              void* d_out, int out_size)
{
    const float* x  = (const float*)d_in[0];
    const float* Wq = (const float*)d_in[1];
    const float* Wk = (const float*)d_in[2];
    const float* Wv = (const float*)d_in[3];
    const float* Wo = (const float*)d_in[4];
    const float* bo = (const float*)d_in[5];
    float* out = (float*)d_out;

    cudaFuncSetAttribute(flash_mma_kernel,
                         cudaFuncAttributeMaxDynamicSharedMemorySize, FLASH_SMEM_BYTES);

    dim3 gq(Cn / 128, (Bn * Tn) / 128, 3);
    qkv_mma_kernel<<<gq, 256>>>(x, Wq, Wk, Wv);

    dim3 ga(Tn / 64, Hn, Bn);
    flash_mma_kernel<<<ga, 128, FLASH_SMEM_BYTES>>>();

    dim3 go(Cn / 128, (Bn * Tn) / 128);
    oproj_mma_kernel<<<go, 256>>>(Wo, bo, out);
}